// round 6
// baseline (speedup 1.0000x reference)
#include <cuda_runtime.h>
#include <cuda_bf16.h>
#include <cstdint>

#define N_TOK 10368
#define CDIM  256
#define HDIM  128
#define NCHUNK 81
#define CPAD  132

// ---------------- scratch ----------------
__device__ __align__(16) __nv_bfloat16 g_feat_h[(size_t)CDIM * N_TOK];
__device__ __align__(16) __nv_bfloat16 g_feat_l[(size_t)CDIM * N_TOK];
__device__ __align__(16) __nv_bfloat16 g_Wh[(size_t)CDIM * CDIM];   // rows 0-127 Wi, 128-255 Wj
__device__ __align__(16) __nv_bfloat16 g_Wl[(size_t)CDIM * CDIM];
__device__ __align__(16) __nv_bfloat16 g_Fh[(size_t)CDIM * N_TOK];  // rows 0-127 Fi, 128-255 Fj
__device__ __align__(16) __nv_bfloat16 g_Fl[(size_t)CDIM * N_TOK];
__device__ float g_Gpart[(size_t)NCHUNK * HDIM * CDIM];             // [z][p][q] fp32
__device__ __align__(16) __nv_bfloat16 g_Gh[(size_t)HDIM * CDIM];   // G/N as bf16 hi/lo
__device__ __align__(16) __nv_bfloat16 g_Gl[(size_t)HDIM * CDIM];

// ---------------- helpers ----------------
__device__ __forceinline__ uint32_t smem_u32(const void* p) {
    uint32_t a;
    asm("{ .reg .u64 t; cvta.to.shared.u64 t, %1; cvt.u32.u64 %0, t; }" : "=r"(a) : "l"(p));
    return a;
}
__device__ __forceinline__ void ldsm4(uint32_t* r, uint32_t a) {
    asm volatile("ldmatrix.sync.aligned.m8n8.x4.shared.b16 {%0,%1,%2,%3}, [%4];"
                 : "=r"(r[0]), "=r"(r[1]), "=r"(r[2]), "=r"(r[3]) : "r"(a));
}
__device__ __forceinline__ void ldsm4t(uint32_t* r, uint32_t a) {
    asm volatile("ldmatrix.sync.aligned.m8n8.x4.trans.shared.b16 {%0,%1,%2,%3}, [%4];"
                 : "=r"(r[0]), "=r"(r[1]), "=r"(r[2]), "=r"(r[3]) : "r"(a));
}
__device__ __forceinline__ void mma_bf16(float* d, const uint32_t* a, const uint32_t* b) {
    asm volatile("mma.sync.aligned.m16n8k16.row.col.f32.bf16.bf16.f32 "
                 "{%0,%1,%2,%3}, {%4,%5,%6,%7}, {%8,%9}, {%0,%1,%2,%3};"
                 : "+f"(d[0]), "+f"(d[1]), "+f"(d[2]), "+f"(d[3])
                 : "r"(a[0]), "r"(a[1]), "r"(a[2]), "r"(a[3]), "r"(b[0]), "r"(b[1]));
}
__device__ __forceinline__ void cpa16(uint32_t dst, const void* src) {
    asm volatile("cp.async.cg.shared.global [%0], [%1], 16;" :: "r"(dst), "l"(src));
}
#define CP_COMMIT() asm volatile("cp.async.commit_group;" ::: "memory")
#define CP_WAIT0()  asm volatile("cp.async.wait_group 0;" ::: "memory")

// split fp32x4 into packed bf16 hi and lo (residual) pairs
__device__ __forceinline__ void split4(float4 v, uint2& h, uint2& l) {
    __nv_bfloat16 h0 = __float2bfloat16_rn(v.x), h1 = __float2bfloat16_rn(v.y),
                  h2 = __float2bfloat16_rn(v.z), h3 = __float2bfloat16_rn(v.w);
    float l0 = v.x - __bfloat162float(h0), l1 = v.y - __bfloat162float(h1),
          l2 = v.z - __bfloat162float(h2), l3 = v.w - __bfloat162float(h3);
    h.x = (uint32_t)__bfloat16_as_ushort(h0) | ((uint32_t)__bfloat16_as_ushort(h1) << 16);
    h.y = (uint32_t)__bfloat16_as_ushort(h2) | ((uint32_t)__bfloat16_as_ushort(h3) << 16);
    l.x = (uint32_t)__bfloat16_as_ushort(__float2bfloat16_rn(l0)) |
          ((uint32_t)__bfloat16_as_ushort(__float2bfloat16_rn(l1)) << 16);
    l.y = (uint32_t)__bfloat16_as_ushort(__float2bfloat16_rn(l2)) |
          ((uint32_t)__bfloat16_as_ushort(__float2bfloat16_rn(l3)) << 16);
}

// cp.async a [ROWS x KW] bf16 tile (row stride ld elems) into padded smem (KW+8)
template<int ROWS, int KW>
__device__ __forceinline__ void stage_cp(uint32_t dst, const __nv_bfloat16* __restrict__ src,
                                         int ld, int tid)
{
    constexpr int RV = KW / 8;     // 16B chunks per row
    #pragma unroll
    for (int i = tid; i < ROWS * RV; i += 256) {
        int r = i / RV, c = (i % RV) * 8;
        cpa16(dst + (uint32_t)(r * (KW + 8) + c) * 2, src + (size_t)r * ld + c);
    }
}

// MMA over one staged K=64 chunk (4 k16 steps), warp tile 32x64.
template<bool AT, bool BT, int ASTR, int BSTR>
__device__ __forceinline__ void mma_chunk(float acc[2][8][4],
                                          uint32_t aHi, uint32_t aLo,
                                          uint32_t bHi, uint32_t bLo,
                                          int warp_m, int warp_n, int lane)
{
    const int q = lane >> 3, rr = lane & 7;
    uint32_t aBase, aStep, aM16, bBase, bStep, bN16;
    if (!AT) { aBase = (uint32_t)((warp_m + (q & 1) * 8 + rr) * ASTR + (q >> 1) * 8) * 2;
               aStep = 32; aM16 = 16 * ASTR * 2; }
    else     { aBase = (uint32_t)(((q >> 1) * 8 + rr) * ASTR + warp_m + (q & 1) * 8) * 2;
               aStep = 16 * ASTR * 2; aM16 = 32; }
    if (!BT) { bBase = (uint32_t)((warp_n + (q >> 1) * 8 + rr) * BSTR + (q & 1) * 8) * 2;
               bStep = 32; bN16 = 16 * BSTR * 2; }
    else     { bBase = (uint32_t)(((q & 1) * 8 + rr) * BSTR + warp_n + (q >> 1) * 8) * 2;
               bStep = 16 * BSTR * 2; bN16 = 32; }

    #pragma unroll
    for (int ks = 0; ks < 4; ++ks) {
        uint32_t ah[2][4], al[2][4], bh[16], bl[16];
        uint32_t aA = aBase + ks * aStep, bA = bBase + ks * bStep;
        if (AT) { ldsm4t(ah[0], aHi + aA); ldsm4t(ah[1], aHi + aA + aM16);
                  ldsm4t(al[0], aLo + aA); ldsm4t(al[1], aLo + aA + aM16); }
        else    { ldsm4 (ah[0], aHi + aA); ldsm4 (ah[1], aHi + aA + aM16);
                  ldsm4 (al[0], aLo + aA); ldsm4 (al[1], aLo + aA + aM16); }
        #pragma unroll
        for (int n2 = 0; n2 < 4; ++n2) {
            if (BT) { ldsm4t(bh + n2 * 4, bHi + bA + n2 * bN16);
                      ldsm4t(bl + n2 * 4, bLo + bA + n2 * bN16); }
            else    { ldsm4 (bh + n2 * 4, bHi + bA + n2 * bN16);
                      ldsm4 (bl + n2 * 4, bLo + bA + n2 * bN16); }
        }
        #pragma unroll
        for (int mf = 0; mf < 2; ++mf)
            #pragma unroll
            for (int nf = 0; nf < 8; ++nf) {
                mma_bf16(acc[mf][nf], ah[mf], bh + nf * 2);
                mma_bf16(acc[mf][nf], ah[mf], bl + nf * 2);
                mma_bf16(acc[mf][nf], al[mf], bh + nf * 2);
            }
    }
}

__device__ __forceinline__ void acc_to_smem(float* Cs, float acc[2][8][4],
                                            int warp_m, int warp_n, int lane)
{
    const int lr = lane >> 2, lc = (lane & 3) * 2;
    #pragma unroll
    for (int mf = 0; mf < 2; ++mf)
        #pragma unroll
        for (int nf = 0; nf < 8; ++nf) {
            int m = warp_m + mf * 16 + lr;
            int n = warp_n + nf * 8 + lc;
            float* a = acc[mf][nf];
            *(float2*)(Cs + m * CPAD + n)       = make_float2(a[0], a[1]);
            *(float2*)(Cs + (m + 8) * CPAD + n) = make_float2(a[2], a[3]);
        }
}

// ---------------------------------------------------------------------------
// K0: precompute bf16 hi/lo planes for feat and W
// ---------------------------------------------------------------------------
#define FEAT_V4 (CDIM * N_TOK / 4)      // 663552
#define FEAT_BLK (FEAT_V4 / 256)        // 2592
__global__ __launch_bounds__(256)
void k_cvt(const float* __restrict__ feat,
           const float* __restrict__ Wi, const float* __restrict__ Wj)
{
    int t = blockIdx.x * 256 + threadIdx.x;
    if (blockIdx.x < FEAT_BLK) {
        float4 v = ((const float4*)feat)[t];
        uint2 h, l; split4(v, h, l);
        ((uint2*)g_feat_h)[t] = h;
        ((uint2*)g_feat_l)[t] = l;
    } else {
        int w = t - FEAT_V4;            // 0..16383 float4s of W (Wi then Wj)
        float4 v = (w < 8192) ? ((const float4*)Wi)[w] : ((const float4*)Wj)[w - 8192];
        uint2 h, l; split4(v, h, l);
        ((uint2*)g_Wh)[w] = h;
        ((uint2*)g_Wl)[w] = l;
    }
}

// ---------------------------------------------------------------------------
// K1: F[p][n] = W_half @ feat + bias ; K=256 (4x64). Writes bf16 hi/lo planes.
// ---------------------------------------------------------------------------
__global__ __launch_bounds__(256, 2)
void k_F(const float* __restrict__ bi, const float* __restrict__ bj)
{
    extern __shared__ __align__(16) char smem[];
    const uint32_t sb = smem_u32(smem);
    const uint32_t A_HI = 0, A_LO = 18432, B_HI = 36864, B_LO = 54272;  // A:128x72, B:64x136
    float* Cs = (float*)smem;
    const int tid = threadIdx.x, lane = tid & 31, warp = tid >> 5;
    const int warp_m = (warp >> 1) * 32, warp_n = (warp & 1) * 64;
    const int n0 = blockIdx.x * 128, half = blockIdx.y;
    const float* bias = half ? bj : bi;

    float acc[2][8][4] = {};

    #pragma unroll
    for (int c = 0; c < 4; ++c) {
        if (c) __syncthreads();
        stage_cp<128, 64>(sb + A_HI, g_Wh + (size_t)half * 128 * CDIM + c * 64, CDIM, tid);
        stage_cp<128, 64>(sb + A_LO, g_Wl + (size_t)half * 128 * CDIM + c * 64, CDIM, tid);
        stage_cp<64, 128>(sb + B_HI, g_feat_h + (size_t)(c * 64) * N_TOK + n0, N_TOK, tid);
        stage_cp<64, 128>(sb + B_LO, g_feat_l + (size_t)(c * 64) * N_TOK + n0, N_TOK, tid);
        CP_COMMIT(); CP_WAIT0();
        __syncthreads();
        mma_chunk<false, true, 72, 136>(acc, sb + A_HI, sb + A_LO, sb + B_HI, sb + B_LO,
                                        warp_m, warp_n, lane);
    }

    {   // bias
        const int lr = lane >> 2;
        #pragma unroll
        for (int mf = 0; mf < 2; ++mf) {
            float b0 = bias[warp_m + mf * 16 + lr];
            float b1 = bias[warp_m + mf * 16 + lr + 8];
            #pragma unroll
            for (int nf = 0; nf < 8; ++nf) {
                acc[mf][nf][0] += b0; acc[mf][nf][1] += b0;
                acc[mf][nf][2] += b1; acc[mf][nf][3] += b1;
            }
        }
    }

    __syncthreads();
    acc_to_smem(Cs, acc, warp_m, warp_n, lane);
    __syncthreads();
    for (int i = tid; i < 128 * 32; i += 256) {
        int row = i >> 5, col = (i & 31) << 2;
        float4 v = *(float4*)(Cs + row * CPAD + col);
        uint2 h, l; split4(v, h, l);
        size_t o = (size_t)(half * 128 + row) * N_TOK + n0 + col;
        *(uint2*)(g_Fh + o) = h;
        *(uint2*)(g_Fl + o) = l;
    }
}

// ---------------------------------------------------------------------------
// K2: Gpart[z][p][q] ; M=p(128), N=q(128), K=128 tokens (2x64)
// ---------------------------------------------------------------------------
__global__ __launch_bounds__(256, 2)
void k_Gpart()
{
    extern __shared__ __align__(16) char smem[];
    const uint32_t sb = smem_u32(smem);
    const uint32_t A_HI = 0, A_LO = 18432, B_HI = 36864, B_LO = 55296;  // both 128x72
    float* Cs = (float*)smem;
    const int tid = threadIdx.x, lane = tid & 31, warp = tid >> 5;
    const int warp_m = (warp >> 1) * 32, warp_n = (warp & 1) * 64;
    const int z = blockIdx.x, qh = blockIdx.y;

    float acc[2][8][4] = {};

    #pragma unroll
    for (int c = 0; c < 2; ++c) {
        if (c) __syncthreads();
        stage_cp<128, 64>(sb + A_HI, g_Fh + (size_t)HDIM * N_TOK + z * 128 + c * 64, N_TOK, tid);
        stage_cp<128, 64>(sb + A_LO, g_Fl + (size_t)HDIM * N_TOK + z * 128 + c * 64, N_TOK, tid);
        stage_cp<128, 64>(sb + B_HI, g_feat_h + (size_t)(qh * 128) * N_TOK + z * 128 + c * 64, N_TOK, tid);
        stage_cp<128, 64>(sb + B_LO, g_feat_l + (size_t)(qh * 128) * N_TOK + z * 128 + c * 64, N_TOK, tid);
        CP_COMMIT(); CP_WAIT0();
        __syncthreads();
        mma_chunk<false, false, 72, 72>(acc, sb + A_HI, sb + A_LO, sb + B_HI, sb + B_LO,
                                        warp_m, warp_n, lane);
    }

    __syncthreads();
    acc_to_smem(Cs, acc, warp_m, warp_n, lane);
    __syncthreads();
    float* outp = g_Gpart + (size_t)z * HDIM * CDIM + qh * 128;
    for (int i = tid; i < 128 * 32; i += 256) {
        int row = i >> 5, col = (i & 31) << 2;
        float4 v = *(float4*)(Cs + row * CPAD + col);
        *(float4*)(outp + (size_t)row * CDIM + col) = v;
    }
}

// ---------------------------------------------------------------------------
// K3: G = (1/N) sum_z Gpart ; writes bf16 hi/lo planes
// ---------------------------------------------------------------------------
__global__ __launch_bounds__(256)
void k_R()
{
    const int t = blockIdx.x * 256 + threadIdx.x;   // 0..8191 float4 slots
    const float4* gp = (const float4*)g_Gpart;
    float4 a0 = {0,0,0,0}, a1 = {0,0,0,0}, a2 = {0,0,0,0};
    #pragma unroll 3
    for (int z = 0; z < NCHUNK; z += 3) {
        float4 v0 = gp[(size_t)z * 8192 + t];
        float4 v1 = gp[(size_t)(z + 1) * 8192 + t];
        float4 v2 = gp[(size_t)(z + 2) * 8192 + t];
        a0.x += v0.x; a0.y += v0.y; a0.z += v0.z; a0.w += v0.w;
        a1.x += v1.x; a1.y += v1.y; a1.z += v1.z; a1.w += v1.w;
        a2.x += v2.x; a2.y += v2.y; a2.z += v2.z; a2.w += v2.w;
    }
    const float s = 1.0f / N_TOK;
    float4 r = make_float4((a0.x + a1.x + a2.x) * s, (a0.y + a1.y + a2.y) * s,
                           (a0.z + a1.z + a2.z) * s, (a0.w + a1.w + a2.w) * s);
    uint2 h, l; split4(r, h, l);
    ((uint2*)g_Gh)[t] = h;
    ((uint2*)g_Gl)[t] = l;
}

// ---------------------------------------------------------------------------
// K4: out[q][n] = feat[q][n] + sum_p G[p][q]*Fi[p][n] ; K=128 (2x64), A,B trans
// ---------------------------------------------------------------------------
__global__ __launch_bounds__(256, 2)
void k_out(const float* __restrict__ feat, float* __restrict__ outp)
{
    extern __shared__ __align__(16) char smem[];
    const uint32_t sb = smem_u32(smem);
    const uint32_t A_HI = 0, A_LO = 17408, B_HI = 34816, B_LO = 52224;  // both 64x136
    float* Cs = (float*)smem;
    const int tid = threadIdx.x, lane = tid & 31, warp = tid >> 5;
    const int warp_m = (warp >> 1) * 32, warp_n = (warp & 1) * 64;
    const int n0 = blockIdx.x * 128, half = blockIdx.y;

    float acc[2][8][4] = {};

    #pragma unroll
    for (int c = 0; c < 2; ++c) {
        if (c) __syncthreads();
        stage_cp<64, 128>(sb + A_HI, g_Gh + (size_t)(c * 64) * CDIM + half * 128, CDIM, tid);
        stage_cp<64, 128>(sb + A_LO, g_Gl + (size_t)(c * 64) * CDIM + half * 128, CDIM, tid);
        stage_cp<64, 128>(sb + B_HI, g_Fh + (size_t)(c * 64) * N_TOK + n0, N_TOK, tid);
        stage_cp<64, 128>(sb + B_LO, g_Fl + (size_t)(c * 64) * N_TOK + n0, N_TOK, tid);
        CP_COMMIT(); CP_WAIT0();
        __syncthreads();
        mma_chunk<true, true, 136, 136>(acc, sb + A_HI, sb + A_LO, sb + B_HI, sb + B_LO,
                                        warp_m, warp_n, lane);
    }

    __syncthreads();
    acc_to_smem(Cs, acc, warp_m, warp_n, lane);
    __syncthreads();
    for (int i = tid; i < 128 * 32; i += 256) {
        int row = i >> 5, col = (i & 31) << 2;
        size_t off = (size_t)(half * 128 + row) * N_TOK + n0 + col;
        float4 v = *(float4*)(Cs + row * CPAD + col);
        float4 f = *(const float4*)(feat + off);
        v.x += f.x; v.y += f.y; v.z += f.z; v.w += f.w;
        *(float4*)(outp + off) = v;
    }
}

// ---------------------------------------------------------------------------
extern "C" void kernel_launch(void* const* d_in, const int* in_sizes, int n_in,
                              void* d_out, int out_size)
{
    const float* feat = (const float*)d_in[0];
    const float* Wi   = (const float*)d_in[1];
    const float* bi   = (const float*)d_in[2];
    const float* Wj   = (const float*)d_in[3];
    const float* bj   = (const float*)d_in[4];
    float* outp = (float*)d_out;

    static bool attr_set = false;
    if (!attr_set) {
        cudaFuncSetAttribute(k_F,     cudaFuncAttributeMaxDynamicSharedMemorySize, 71680);
        cudaFuncSetAttribute(k_Gpart, cudaFuncAttributeMaxDynamicSharedMemorySize, 73728);
        cudaFuncSetAttribute(k_out,   cudaFuncAttributeMaxDynamicSharedMemorySize, 69632);
        attr_set = true;
    }

    k_cvt   <<<FEAT_BLK + 64, 256>>>(feat, Wi, Wj);
    k_F     <<<dim3(81, 2), 256, 71680>>>(bi, bj);
    k_Gpart <<<dim3(81, 2), 256, 73728>>>();
    k_R     <<<32, 256>>>();
    k_out   <<<dim3(81, 2), 256, 69632>>>(feat, outp);
}

// round 7
// speedup vs baseline: 1.1652x; 1.1652x over previous
#include <cuda_runtime.h>
#include <cuda_bf16.h>
#include <cstdint>

#define N_TOK 10368
#define CDIM  256
#define HDIM  128
#define NCHUNK 81
#define CPAD  132

// ---------------- scratch ----------------
__device__ __align__(16) __nv_bfloat16 g_feat_h[(size_t)CDIM * N_TOK];
__device__ __align__(16) __nv_bfloat16 g_feat_l[(size_t)CDIM * N_TOK];
__device__ __align__(16) __nv_bfloat16 g_Wh[(size_t)CDIM * CDIM];   // rows 0-127 Wi, 128-255 Wj
__device__ __align__(16) __nv_bfloat16 g_Wl[(size_t)CDIM * CDIM];
__device__ __align__(16) __nv_bfloat16 g_Fh[(size_t)CDIM * N_TOK];  // rows 0-127 Fi, 128-255 Fj
__device__ __align__(16) __nv_bfloat16 g_Fl[(size_t)CDIM * N_TOK];
__device__ float g_Gpart [(size_t)NCHUNK * HDIM * CDIM];            // [z][p][q] fp32
__device__ float g_Gpart2[(size_t)9 * HDIM * CDIM];                 // stage-2 partials
__device__ __align__(16) __nv_bfloat16 g_Gh[(size_t)HDIM * CDIM];   // G/N bf16 hi/lo
__device__ __align__(16) __nv_bfloat16 g_Gl[(size_t)HDIM * CDIM];

// ---------------- helpers ----------------
__device__ __forceinline__ uint32_t smem_u32(const void* p) {
    uint32_t a;
    asm("{ .reg .u64 t; cvta.to.shared.u64 t, %1; cvt.u32.u64 %0, t; }" : "=r"(a) : "l"(p));
    return a;
}
__device__ __forceinline__ void ldsm4(uint32_t* r, uint32_t a) {
    asm volatile("ldmatrix.sync.aligned.m8n8.x4.shared.b16 {%0,%1,%2,%3}, [%4];"
                 : "=r"(r[0]), "=r"(r[1]), "=r"(r[2]), "=r"(r[3]) : "r"(a));
}
__device__ __forceinline__ void ldsm4t(uint32_t* r, uint32_t a) {
    asm volatile("ldmatrix.sync.aligned.m8n8.x4.trans.shared.b16 {%0,%1,%2,%3}, [%4];"
                 : "=r"(r[0]), "=r"(r[1]), "=r"(r[2]), "=r"(r[3]) : "r"(a));
}
__device__ __forceinline__ void mma_bf16(float* d, const uint32_t* a, const uint32_t* b) {
    asm volatile("mma.sync.aligned.m16n8k16.row.col.f32.bf16.bf16.f32 "
                 "{%0,%1,%2,%3}, {%4,%5,%6,%7}, {%8,%9}, {%0,%1,%2,%3};"
                 : "+f"(d[0]), "+f"(d[1]), "+f"(d[2]), "+f"(d[3])
                 : "r"(a[0]), "r"(a[1]), "r"(a[2]), "r"(a[3]), "r"(b[0]), "r"(b[1]));
}
__device__ __forceinline__ void cpa16(uint32_t dst, const void* src) {
    asm volatile("cp.async.cg.shared.global [%0], [%1], 16;" :: "r"(dst), "l"(src));
}
#define CP_COMMIT() asm volatile("cp.async.commit_group;" ::: "memory")
#define CP_WAIT0()  asm volatile("cp.async.wait_group 0;" ::: "memory")
#define CP_WAIT1()  asm volatile("cp.async.wait_group 1;" ::: "memory")

__device__ __forceinline__ void split4(float4 v, uint2& h, uint2& l) {
    __nv_bfloat16 h0 = __float2bfloat16_rn(v.x), h1 = __float2bfloat16_rn(v.y),
                  h2 = __float2bfloat16_rn(v.z), h3 = __float2bfloat16_rn(v.w);
    float l0 = v.x - __bfloat162float(h0), l1 = v.y - __bfloat162float(h1),
          l2 = v.z - __bfloat162float(h2), l3 = v.w - __bfloat162float(h3);
    h.x = (uint32_t)__bfloat16_as_ushort(h0) | ((uint32_t)__bfloat16_as_ushort(h1) << 16);
    h.y = (uint32_t)__bfloat16_as_ushort(h2) | ((uint32_t)__bfloat16_as_ushort(h3) << 16);
    l.x = (uint32_t)__bfloat16_as_ushort(__float2bfloat16_rn(l0)) |
          ((uint32_t)__bfloat16_as_ushort(__float2bfloat16_rn(l1)) << 16);
    l.y = (uint32_t)__bfloat16_as_ushort(__float2bfloat16_rn(l2)) |
          ((uint32_t)__bfloat16_as_ushort(__float2bfloat16_rn(l3)) << 16);
}

// cp.async a [ROWS x KW] bf16 tile (row stride ld elems) into padded smem (KW+8)
template<int ROWS, int KW>
__device__ __forceinline__ void stage_cp(uint32_t dst, const __nv_bfloat16* __restrict__ src,
                                         int ld, int tid)
{
    constexpr int RV = KW / 8;
    #pragma unroll
    for (int i = tid; i < ROWS * RV; i += 256) {
        int r = i / RV, c = (i % RV) * 8;
        cpa16(dst + (uint32_t)(r * (KW + 8) + c) * 2, src + (size_t)r * ld + c);
    }
}

// MMA over one staged K=32 chunk (KSTEPS=2 k16 steps), warp tile 32x64.
template<bool AT, bool BT, int ASTR, int BSTR>
__device__ __forceinline__ void mma_chunk(float acc[2][8][4],
                                          uint32_t aHi, uint32_t aLo,
                                          uint32_t bHi, uint32_t bLo,
                                          int warp_m, int warp_n, int lane)
{
    const int q = lane >> 3, rr = lane & 7;
    uint32_t aBase, aStep, aM16, bBase, bStep, bN16;
    if (!AT) { aBase = (uint32_t)((warp_m + (q & 1) * 8 + rr) * ASTR + (q >> 1) * 8) * 2;
               aStep = 32; aM16 = 16 * ASTR * 2; }
    else     { aBase = (uint32_t)(((q >> 1) * 8 + rr) * ASTR + warp_m + (q & 1) * 8) * 2;
               aStep = 16 * ASTR * 2; aM16 = 32; }
    if (!BT) { bBase = (uint32_t)((warp_n + (q >> 1) * 8 + rr) * BSTR + (q & 1) * 8) * 2;
               bStep = 32; bN16 = 16 * BSTR * 2; }
    else     { bBase = (uint32_t)(((q & 1) * 8 + rr) * BSTR + warp_n + (q >> 1) * 8) * 2;
               bStep = 16 * BSTR * 2; bN16 = 32; }

    #pragma unroll
    for (int ks = 0; ks < 2; ++ks) {
        uint32_t ah[2][4], al[2][4], bh[16], bl[16];
        uint32_t aA = aBase + ks * aStep, bA = bBase + ks * bStep;
        if (AT) { ldsm4t(ah[0], aHi + aA); ldsm4t(ah[1], aHi + aA + aM16);
                  ldsm4t(al[0], aLo + aA); ldsm4t(al[1], aLo + aA + aM16); }
        else    { ldsm4 (ah[0], aHi + aA); ldsm4 (ah[1], aHi + aA + aM16);
                  ldsm4 (al[0], aLo + aA); ldsm4 (al[1], aLo + aA + aM16); }
        #pragma unroll
        for (int n2 = 0; n2 < 4; ++n2) {
            if (BT) { ldsm4t(bh + n2 * 4, bHi + bA + n2 * bN16);
                      ldsm4t(bl + n2 * 4, bLo + bA + n2 * bN16); }
            else    { ldsm4 (bh + n2 * 4, bHi + bA + n2 * bN16);
                      ldsm4 (bl + n2 * 4, bLo + bA + n2 * bN16); }
        }
        #pragma unroll
        for (int mf = 0; mf < 2; ++mf)
            #pragma unroll
            for (int nf = 0; nf < 8; ++nf) {
                mma_bf16(acc[mf][nf], ah[mf], bh + nf * 2);
                mma_bf16(acc[mf][nf], ah[mf], bl + nf * 2);
                mma_bf16(acc[mf][nf], al[mf], bh + nf * 2);
            }
    }
}

__device__ __forceinline__ void acc_to_smem(float* Cs, float acc[2][8][4],
                                            int warp_m, int warp_n, int lane)
{
    const int lr = lane >> 2, lc = (lane & 3) * 2;
    #pragma unroll
    for (int mf = 0; mf < 2; ++mf)
        #pragma unroll
        for (int nf = 0; nf < 8; ++nf) {
            int m = warp_m + mf * 16 + lr;
            int n = warp_n + nf * 8 + lc;
            float* a = acc[mf][nf];
            *(float2*)(Cs + m * CPAD + n)       = make_float2(a[0], a[1]);
            *(float2*)(Cs + (m + 8) * CPAD + n) = make_float2(a[2], a[3]);
        }
}

// ---------------------------------------------------------------------------
// K0: precompute bf16 hi/lo planes for feat and W
// ---------------------------------------------------------------------------
#define FEAT_V4 (CDIM * N_TOK / 4)
#define FEAT_BLK (FEAT_V4 / 256)
__global__ __launch_bounds__(256)
void k_cvt(const float* __restrict__ feat,
           const float* __restrict__ Wi, const float* __restrict__ Wj)
{
    int t = blockIdx.x * 256 + threadIdx.x;
    if (blockIdx.x < FEAT_BLK) {
        float4 v = ((const float4*)feat)[t];
        uint2 h, l; split4(v, h, l);
        ((uint2*)g_feat_h)[t] = h;
        ((uint2*)g_feat_l)[t] = l;
    } else {
        int w = t - FEAT_V4;
        float4 v = (w < 8192) ? ((const float4*)Wi)[w] : ((const float4*)Wj)[w - 8192];
        uint2 h, l; split4(v, h, l);
        ((uint2*)g_Wh)[w] = h;
        ((uint2*)g_Wl)[w] = l;
    }
}

// ---------------------------------------------------------------------------
// K1: F[p][n] = W_half @ feat + bias ; K=256 -> 8 chunks of 32, double-buffered
//   chunk buf: A(hi,lo) 128x40 = 10240B each, B(hi,lo) 32x136 = 8704B each
// ---------------------------------------------------------------------------
#define F_CH   37888
#define F_A_LO 10240
#define F_B_HI 20480
#define F_B_LO 29184
__global__ __launch_bounds__(256, 2)
void k_F(const float* __restrict__ bi, const float* __restrict__ bj)
{
    extern __shared__ __align__(16) char smem[];
    const uint32_t sb = smem_u32(smem);
    float* Cs = (float*)smem;
    const int tid = threadIdx.x, lane = tid & 31, warp = tid >> 5;
    const int warp_m = (warp >> 1) * 32, warp_n = (warp & 1) * 64;
    const int n0 = blockIdx.x * 128, half = blockIdx.y;
    const float* bias = half ? bj : bi;
    const __nv_bfloat16* Wh = g_Wh + (size_t)half * 128 * CDIM;
    const __nv_bfloat16* Wl = g_Wl + (size_t)half * 128 * CDIM;

    float acc[2][8][4] = {};

    auto prefetch = [&](int c, uint32_t buf) {
        stage_cp<128, 32>(buf,          Wh + c * 32, CDIM, tid);
        stage_cp<128, 32>(buf + F_A_LO, Wl + c * 32, CDIM, tid);
        stage_cp<32, 128>(buf + F_B_HI, g_feat_h + (size_t)(c * 32) * N_TOK + n0, N_TOK, tid);
        stage_cp<32, 128>(buf + F_B_LO, g_feat_l + (size_t)(c * 32) * N_TOK + n0, N_TOK, tid);
        CP_COMMIT();
    };

    prefetch(0, sb);
    #pragma unroll
    for (int c = 0; c < 8; ++c) {
        uint32_t cur = sb + (c & 1) * F_CH;
        if (c + 1 < 8) { prefetch(c + 1, sb + ((c + 1) & 1) * F_CH); CP_WAIT1(); }
        else           { CP_WAIT0(); }
        __syncthreads();
        mma_chunk<false, true, 40, 136>(acc, cur, cur + F_A_LO, cur + F_B_HI, cur + F_B_LO,
                                        warp_m, warp_n, lane);
        __syncthreads();
    }

    {   // bias
        const int lr = lane >> 2;
        #pragma unroll
        for (int mf = 0; mf < 2; ++mf) {
            float b0 = bias[warp_m + mf * 16 + lr];
            float b1 = bias[warp_m + mf * 16 + lr + 8];
            #pragma unroll
            for (int nf = 0; nf < 8; ++nf) {
                acc[mf][nf][0] += b0; acc[mf][nf][1] += b0;
                acc[mf][nf][2] += b1; acc[mf][nf][3] += b1;
            }
        }
    }

    acc_to_smem(Cs, acc, warp_m, warp_n, lane);
    __syncthreads();
    for (int i = tid; i < 128 * 32; i += 256) {
        int row = i >> 5, col = (i & 31) << 2;
        float4 v = *(float4*)(Cs + row * CPAD + col);
        uint2 h, l; split4(v, h, l);
        size_t o = (size_t)(half * 128 + row) * N_TOK + n0 + col;
        *(uint2*)(g_Fh + o) = h;
        *(uint2*)(g_Fl + o) = l;
    }
}

// ---------------------------------------------------------------------------
// K2: Gpart[z][p][q] ; K=128 tokens -> 4 chunks of 32, double-buffered
//   chunk buf: A(hi,lo) 128x40, B(hi,lo) 128x40 = 10240B each
// ---------------------------------------------------------------------------
#define G_CH   40960
__global__ __launch_bounds__(256, 2)
void k_Gpart()
{
    extern __shared__ __align__(16) char smem[];
    const uint32_t sb = smem_u32(smem);
    float* Cs = (float*)smem;
    const int tid = threadIdx.x, lane = tid & 31, warp = tid >> 5;
    const int warp_m = (warp >> 1) * 32, warp_n = (warp & 1) * 64;
    const int z = blockIdx.x, qh = blockIdx.y;
    const __nv_bfloat16* Ah = g_Fh + (size_t)HDIM * N_TOK + z * 128;
    const __nv_bfloat16* Al = g_Fl + (size_t)HDIM * N_TOK + z * 128;
    const __nv_bfloat16* Bh = g_feat_h + (size_t)(qh * 128) * N_TOK + z * 128;
    const __nv_bfloat16* Bl = g_feat_l + (size_t)(qh * 128) * N_TOK + z * 128;

    float acc[2][8][4] = {};

    auto prefetch = [&](int c, uint32_t buf) {
        stage_cp<128, 32>(buf,         Ah + c * 32, N_TOK, tid);
        stage_cp<128, 32>(buf + 10240, Al + c * 32, N_TOK, tid);
        stage_cp<128, 32>(buf + 20480, Bh + c * 32, N_TOK, tid);
        stage_cp<128, 32>(buf + 30720, Bl + c * 32, N_TOK, tid);
        CP_COMMIT();
    };

    prefetch(0, sb);
    #pragma unroll
    for (int c = 0; c < 4; ++c) {
        uint32_t cur = sb + (c & 1) * G_CH;
        if (c + 1 < 4) { prefetch(c + 1, sb + ((c + 1) & 1) * G_CH); CP_WAIT1(); }
        else           { CP_WAIT0(); }
        __syncthreads();
        mma_chunk<false, false, 40, 40>(acc, cur, cur + 10240, cur + 20480, cur + 30720,
                                        warp_m, warp_n, lane);
        __syncthreads();
    }

    acc_to_smem(Cs, acc, warp_m, warp_n, lane);
    __syncthreads();
    float* outp = g_Gpart + (size_t)z * HDIM * CDIM + qh * 128;
    for (int i = tid; i < 128 * 32; i += 256) {
        int row = i >> 5, col = (i & 31) << 2;
        float4 v = *(float4*)(Cs + row * CPAD + col);
        *(float4*)(outp + (size_t)row * CDIM + col) = v;
    }
}

// ---------------------------------------------------------------------------
// K3a: Gpart2[g] = sum of 9 chunks ; grid (32, 9)
// ---------------------------------------------------------------------------
__global__ __launch_bounds__(256)
void k_R1()
{
    const int t = blockIdx.x * 256 + threadIdx.x;    // 0..8191 float4 slots
    const int g = blockIdx.y;
    const float4* gp = (const float4*)g_Gpart + (size_t)g * 9 * 8192;
    float4 a0 = {0,0,0,0}, a1 = {0,0,0,0}, a2 = {0,0,0,0};
    #pragma unroll
    for (int z = 0; z < 9; z += 3) {
        float4 v0 = gp[(size_t)z * 8192 + t];
        float4 v1 = gp[(size_t)(z + 1) * 8192 + t];
        float4 v2 = gp[(size_t)(z + 2) * 8192 + t];
        a0.x += v0.x; a0.y += v0.y; a0.z += v0.z; a0.w += v0.w;
        a1.x += v1.x; a1.y += v1.y; a1.z += v1.z; a1.w += v1.w;
        a2.x += v2.x; a2.y += v2.y; a2.z += v2.z; a2.w += v2.w;
    }
    float4 r = make_float4(a0.x + a1.x + a2.x, a0.y + a1.y + a2.y,
                           a0.z + a1.z + a2.z, a0.w + a1.w + a2.w);
    ((float4*)g_Gpart2)[(size_t)g * 8192 + t] = r;
}

// ---------------------------------------------------------------------------
// K3b: G = (1/N) * sum of 9 partials -> bf16 hi/lo planes
// ---------------------------------------------------------------------------
__global__ __launch_bounds__(256)
void k_R2()
{
    const int t = blockIdx.x * 256 + threadIdx.x;
    const float4* gp = (const float4*)g_Gpart2;
    float4 a0 = {0,0,0,0}, a1 = {0,0,0,0}, a2 = {0,0,0,0};
    #pragma unroll
    for (int g = 0; g < 9; g += 3) {
        float4 v0 = gp[(size_t)g * 8192 + t];
        float4 v1 = gp[(size_t)(g + 1) * 8192 + t];
        float4 v2 = gp[(size_t)(g + 2) * 8192 + t];
        a0.x += v0.x; a0.y += v0.y; a0.z += v0.z; a0.w += v0.w;
        a1.x += v1.x; a1.y += v1.y; a1.z += v1.z; a1.w += v1.w;
        a2.x += v2.x; a2.y += v2.y; a2.z += v2.z; a2.w += v2.w;
    }
    const float s = 1.0f / N_TOK;
    float4 r = make_float4((a0.x + a1.x + a2.x) * s, (a0.y + a1.y + a2.y) * s,
                           (a0.z + a1.z + a2.z) * s, (a0.w + a1.w + a2.w) * s);
    uint2 h, l; split4(r, h, l);
    ((uint2*)g_Gh)[t] = h;
    ((uint2*)g_Gl)[t] = l;
}

// ---------------------------------------------------------------------------
// K4: out[q][n] = feat[q][n] + sum_p G[p][q]*Fi[p][n] ; 4 chunks of 32, dbl-buf
//   chunk buf: A(hi,lo) 32x136 = 8704B each, B(hi,lo) 32x136 = 8704B each
// ---------------------------------------------------------------------------
#define O_CH 34816
__global__ __launch_bounds__(256, 2)
void k_out(const float* __restrict__ feat, float* __restrict__ outp)
{
    extern __shared__ __align__(16) char smem[];
    const uint32_t sb = smem_u32(smem);
    float* Cs = (float*)smem;
    const int tid = threadIdx.x, lane = tid & 31, warp = tid >> 5;
    const int warp_m = (warp >> 1) * 32, warp_n = (warp & 1) * 64;
    const int n0 = blockIdx.x * 128, half = blockIdx.y;

    float acc[2][8][4] = {};

    auto prefetch = [&](int c, uint32_t buf) {
        stage_cp<32, 128>(buf,         g_Gh + (size_t)(c * 32) * CDIM + half * 128, CDIM, tid);
        stage_cp<32, 128>(buf + 8704,  g_Gl + (size_t)(c * 32) * CDIM + half * 128, CDIM, tid);
        stage_cp<32, 128>(buf + 17408, g_Fh + (size_t)(c * 32) * N_TOK + n0, N_TOK, tid);
        stage_cp<32, 128>(buf + 26112, g_Fl + (size_t)(c * 32) * N_TOK + n0, N_TOK, tid);
        CP_COMMIT();
    };

    prefetch(0, sb);
    #pragma unroll
    for (int c = 0; c < 4; ++c) {
        uint32_t cur = sb + (c & 1) * O_CH;
        if (c + 1 < 4) { prefetch(c + 1, sb + ((c + 1) & 1) * O_CH); CP_WAIT1(); }
        else           { CP_WAIT0(); }
        __syncthreads();
        mma_chunk<true, true, 136, 136>(acc, cur, cur + 8704, cur + 17408, cur + 26112,
                                        warp_m, warp_n, lane);
        __syncthreads();
    }

    acc_to_smem(Cs, acc, warp_m, warp_n, lane);
    __syncthreads();
    for (int i = tid; i < 128 * 32; i += 256) {
        int row = i >> 5, col = (i & 31) << 2;
        size_t off = (size_t)(half * 128 + row) * N_TOK + n0 + col;
        float4 v = *(float4*)(Cs + row * CPAD + col);
        float4 f = *(const float4*)(feat + off);
        v.x += f.x; v.y += f.y; v.z += f.z; v.w += f.w;
        *(float4*)(outp + off) = v;
    }
}

// ---------------------------------------------------------------------------
extern "C" void kernel_launch(void* const* d_in, const int* in_sizes, int n_in,
                              void* d_out, int out_size)
{
    const float* feat = (const float*)d_in[0];
    const float* Wi   = (const float*)d_in[1];
    const float* bi   = (const float*)d_in[2];
    const float* Wj   = (const float*)d_in[3];
    const float* bj   = (const float*)d_in[4];
    float* outp = (float*)d_out;

    static bool attr_set = false;
    if (!attr_set) {
        cudaFuncSetAttribute(k_F,     cudaFuncAttributeMaxDynamicSharedMemorySize, 2 * F_CH);
        cudaFuncSetAttribute(k_Gpart, cudaFuncAttributeMaxDynamicSharedMemorySize, 2 * G_CH);
        cudaFuncSetAttribute(k_out,   cudaFuncAttributeMaxDynamicSharedMemorySize, 2 * O_CH);
        attr_set = true;
    }

    k_cvt   <<<FEAT_BLK + 64, 256>>>(feat, Wi, Wj);
    k_F     <<<dim3(81, 2), 256, 2 * F_CH>>>(bi, bj);
    k_Gpart <<<dim3(81, 2), 256, 2 * G_CH>>>();
    k_R1    <<<dim3(32, 9), 256>>>();
    k_R2    <<<32, 256>>>();
    k_out   <<<dim3(81, 2), 256, 2 * O_CH>>>(feat, outp);
}

// round 8
// speedup vs baseline: 1.3476x; 1.1565x over previous
#include <cuda_runtime.h>
#include <cuda_bf16.h>
#include <cstdint>

#define N_TOK 10368
#define CDIM  256
#define HDIM  128
#define NZ    54          // token chunks of 192 for Gpart
#define CPAD  68

// ---------------- scratch ----------------
__device__ __align__(16) __nv_bfloat16 g_feat_h[(size_t)CDIM * N_TOK];
__device__ __align__(16) __nv_bfloat16 g_feat_l[(size_t)CDIM * N_TOK];
__device__ __align__(16) __nv_bfloat16 g_Wh[(size_t)CDIM * CDIM];   // rows 0-127 Wi, 128-255 Wj
__device__ __align__(16) __nv_bfloat16 g_Wl[(size_t)CDIM * CDIM];
__device__ __align__(16) __nv_bfloat16 g_Fh[(size_t)CDIM * N_TOK];  // rows 0-127 Fi, 128-255 Fj
__device__ __align__(16) __nv_bfloat16 g_Fl[(size_t)CDIM * N_TOK];
__device__ float g_Gpart [(size_t)NZ * HDIM * CDIM];                // [z][p][q] fp32
__device__ float g_Gpart2[(size_t)9 * HDIM * CDIM];
__device__ __align__(16) __nv_bfloat16 g_Gh[(size_t)HDIM * CDIM];   // G/N bf16 hi/lo
__device__ __align__(16) __nv_bfloat16 g_Gl[(size_t)HDIM * CDIM];

// ---------------- helpers ----------------
__device__ __forceinline__ uint32_t smem_u32(const void* p) {
    uint32_t a;
    asm("{ .reg .u64 t; cvta.to.shared.u64 t, %1; cvt.u32.u64 %0, t; }" : "=r"(a) : "l"(p));
    return a;
}
__device__ __forceinline__ void ldsm4(uint32_t* r, uint32_t a) {
    asm volatile("ldmatrix.sync.aligned.m8n8.x4.shared.b16 {%0,%1,%2,%3}, [%4];"
                 : "=r"(r[0]), "=r"(r[1]), "=r"(r[2]), "=r"(r[3]) : "r"(a));
}
__device__ __forceinline__ void ldsm4t(uint32_t* r, uint32_t a) {
    asm volatile("ldmatrix.sync.aligned.m8n8.x4.trans.shared.b16 {%0,%1,%2,%3}, [%4];"
                 : "=r"(r[0]), "=r"(r[1]), "=r"(r[2]), "=r"(r[3]) : "r"(a));
}
__device__ __forceinline__ void mma_bf16(float* d, const uint32_t* a, const uint32_t* b) {
    asm volatile("mma.sync.aligned.m16n8k16.row.col.f32.bf16.bf16.f32 "
                 "{%0,%1,%2,%3}, {%4,%5,%6,%7}, {%8,%9}, {%0,%1,%2,%3};"
                 : "+f"(d[0]), "+f"(d[1]), "+f"(d[2]), "+f"(d[3])
                 : "r"(a[0]), "r"(a[1]), "r"(a[2]), "r"(a[3]), "r"(b[0]), "r"(b[1]));
}
__device__ __forceinline__ void cpa16(uint32_t dst, const void* src) {
    asm volatile("cp.async.cg.shared.global [%0], [%1], 16;" :: "r"(dst), "l"(src));
}
#define CP_COMMIT() asm volatile("cp.async.commit_group;" ::: "memory")
#define CP_WAIT0()  asm volatile("cp.async.wait_group 0;" ::: "memory")
#define CP_WAIT1()  asm volatile("cp.async.wait_group 1;" ::: "memory")

__device__ __forceinline__ void split4(float4 v, uint2& h, uint2& l) {
    __nv_bfloat16 h0 = __float2bfloat16_rn(v.x), h1 = __float2bfloat16_rn(v.y),
                  h2 = __float2bfloat16_rn(v.z), h3 = __float2bfloat16_rn(v.w);
    float l0 = v.x - __bfloat162float(h0), l1 = v.y - __bfloat162float(h1),
          l2 = v.z - __bfloat162float(h2), l3 = v.w - __bfloat162float(h3);
    h.x = (uint32_t)__bfloat16_as_ushort(h0) | ((uint32_t)__bfloat16_as_ushort(h1) << 16);
    h.y = (uint32_t)__bfloat16_as_ushort(h2) | ((uint32_t)__bfloat16_as_ushort(h3) << 16);
    l.x = (uint32_t)__bfloat16_as_ushort(__float2bfloat16_rn(l0)) |
          ((uint32_t)__bfloat16_as_ushort(__float2bfloat16_rn(l1)) << 16);
    l.y = (uint32_t)__bfloat16_as_ushort(__float2bfloat16_rn(l2)) |
          ((uint32_t)__bfloat16_as_ushort(__float2bfloat16_rn(l3)) << 16);
}

// cp.async a [ROWS x KW] bf16 tile (row stride ld elems) into padded smem (KW+8)
template<int ROWS, int KW>
__device__ __forceinline__ void stage_cp(uint32_t dst, const __nv_bfloat16* __restrict__ src,
                                         int ld, int tid)
{
    constexpr int RV = KW / 8;
    #pragma unroll
    for (int i = tid; i < ROWS * RV; i += 256) {
        int r = i / RV, c = (i % RV) * 8;
        cpa16(dst + (uint32_t)(r * (KW + 8) + c) * 2, src + (size_t)r * ld + c);
    }
}

// MMA over one staged K=32 chunk (2 k16 steps). Warp tile (MF*16) x (NF2*16).
template<int MF, int NF2, bool AT, bool BT, int ASTR, int BSTR>
__device__ __forceinline__ void mma_chunk(float acc[MF][NF2 * 2][4],
                                          uint32_t aHi, uint32_t aLo,
                                          uint32_t bHi, uint32_t bLo,
                                          int warp_m, int warp_n, int lane)
{
    const int q = lane >> 3, rr = lane & 7;
    uint32_t aBase, aStep, aM16, bBase, bStep, bN16;
    if (!AT) { aBase = (uint32_t)((warp_m + (q & 1) * 8 + rr) * ASTR + (q >> 1) * 8) * 2;
               aStep = 32; aM16 = 16 * ASTR * 2; }
    else     { aBase = (uint32_t)(((q >> 1) * 8 + rr) * ASTR + warp_m + (q & 1) * 8) * 2;
               aStep = 16 * ASTR * 2; aM16 = 32; }
    if (!BT) { bBase = (uint32_t)((warp_n + (q >> 1) * 8 + rr) * BSTR + (q & 1) * 8) * 2;
               bStep = 32; bN16 = 16 * BSTR * 2; }
    else     { bBase = (uint32_t)(((q & 1) * 8 + rr) * BSTR + warp_n + (q >> 1) * 8) * 2;
               bStep = 16 * BSTR * 2; bN16 = 32; }

    #pragma unroll
    for (int ks = 0; ks < 2; ++ks) {
        uint32_t ah[MF][4], al[MF][4], bh[NF2][4], bl[NF2][4];
        uint32_t aA = aBase + ks * aStep, bA = bBase + ks * bStep;
        #pragma unroll
        for (int i = 0; i < MF; ++i) {
            if (AT) { ldsm4t(ah[i], aHi + aA + i * aM16); ldsm4t(al[i], aLo + aA + i * aM16); }
            else    { ldsm4 (ah[i], aHi + aA + i * aM16); ldsm4 (al[i], aLo + aA + i * aM16); }
        }
        #pragma unroll
        for (int g = 0; g < NF2; ++g) {
            if (BT) { ldsm4t(bh[g], bHi + bA + g * bN16); ldsm4t(bl[g], bLo + bA + g * bN16); }
            else    { ldsm4 (bh[g], bHi + bA + g * bN16); ldsm4 (bl[g], bLo + bA + g * bN16); }
        }
        #pragma unroll
        for (int i = 0; i < MF; ++i)
            #pragma unroll
            for (int j = 0; j < NF2 * 2; ++j) {
                mma_bf16(acc[i][j], ah[i], &bh[j >> 1][(j & 1) * 2]);
                mma_bf16(acc[i][j], ah[i], &bl[j >> 1][(j & 1) * 2]);
                mma_bf16(acc[i][j], al[i], &bh[j >> 1][(j & 1) * 2]);
            }
    }
}

template<int MF, int NF>
__device__ __forceinline__ void acc_to_smem(float* Cs, float acc[MF][NF][4],
                                            int warp_m, int warp_n, int lane)
{
    const int lr = lane >> 2, lc = (lane & 3) * 2;
    #pragma unroll
    for (int i = 0; i < MF; ++i)
        #pragma unroll
        for (int j = 0; j < NF; ++j) {
            int m = warp_m + i * 16 + lr;
            int n = warp_n + j * 8 + lc;
            float* a = acc[i][j];
            *(float2*)(Cs + m * CPAD + n)       = make_float2(a[0], a[1]);
            *(float2*)(Cs + (m + 8) * CPAD + n) = make_float2(a[2], a[3]);
        }
}

// ---------------------------------------------------------------------------
// K0: precompute bf16 hi/lo planes for feat and W
// ---------------------------------------------------------------------------
#define FEAT_V4 (CDIM * N_TOK / 4)
#define FEAT_BLK (FEAT_V4 / 256)
__global__ __launch_bounds__(256)
void k_cvt(const float* __restrict__ feat,
           const float* __restrict__ Wi, const float* __restrict__ Wj)
{
    int t = blockIdx.x * 256 + threadIdx.x;
    if (blockIdx.x < FEAT_BLK) {
        float4 v = ((const float4*)feat)[t];
        uint2 h, l; split4(v, h, l);
        ((uint2*)g_feat_h)[t] = h;
        ((uint2*)g_feat_l)[t] = l;
    } else {
        int w = t - FEAT_V4;
        float4 v = (w < 8192) ? ((const float4*)Wi)[w] : ((const float4*)Wj)[w - 8192];
        uint2 h, l; split4(v, h, l);
        ((uint2*)g_Wh)[w] = h;
        ((uint2*)g_Wl)[w] = l;
    }
}

// ---------------------------------------------------------------------------
// K1: F = W_half @ feat + bias ; grid (162, 2), tile 128(m) x 64(n), 8 K-chunks
//   buf: A(hi,lo) 128x40 = 10240B each ; B(hi,lo) 32x72 = 4608B each
// ---------------------------------------------------------------------------
#define F_CH 29696
__global__ __launch_bounds__(256, 2)
void k_F(const float* __restrict__ bi, const float* __restrict__ bj)
{
    extern __shared__ __align__(16) char smem[];
    const uint32_t sb = smem_u32(smem);
    float* Cs = (float*)smem;
    const int tid = threadIdx.x, lane = tid & 31, warp = tid >> 5;
    const int warp_m = (warp >> 1) * 32, warp_n = (warp & 1) * 32;
    const int n0 = blockIdx.x * 64, half = blockIdx.y;
    const float* bias = half ? bj : bi;
    const __nv_bfloat16* Wh = g_Wh + (size_t)half * 128 * CDIM;
    const __nv_bfloat16* Wl = g_Wl + (size_t)half * 128 * CDIM;

    float acc[2][4][4] = {};

    auto prefetch = [&](int c, uint32_t buf) {
        stage_cp<128, 32>(buf,         Wh + c * 32, CDIM, tid);
        stage_cp<128, 32>(buf + 10240, Wl + c * 32, CDIM, tid);
        stage_cp<32, 64>(buf + 20480, g_feat_h + (size_t)(c * 32) * N_TOK + n0, N_TOK, tid);
        stage_cp<32, 64>(buf + 25088, g_feat_l + (size_t)(c * 32) * N_TOK + n0, N_TOK, tid);
        CP_COMMIT();
    };

    prefetch(0, sb);
    #pragma unroll
    for (int c = 0; c < 8; ++c) {
        uint32_t cur = sb + (c & 1) * F_CH;
        if (c + 1 < 8) { prefetch(c + 1, sb + ((c + 1) & 1) * F_CH); CP_WAIT1(); }
        else           { CP_WAIT0(); }
        __syncthreads();
        mma_chunk<2, 2, false, true, 40, 72>(acc, cur, cur + 10240, cur + 20480, cur + 25088,
                                             warp_m, warp_n, lane);
        __syncthreads();
    }

    {   // bias
        const int lr = lane >> 2;
        #pragma unroll
        for (int i = 0; i < 2; ++i) {
            float b0 = bias[warp_m + i * 16 + lr];
            float b1 = bias[warp_m + i * 16 + lr + 8];
            #pragma unroll
            for (int j = 0; j < 4; ++j) {
                acc[i][j][0] += b0; acc[i][j][1] += b0;
                acc[i][j][2] += b1; acc[i][j][3] += b1;
            }
        }
    }

    acc_to_smem<2, 4>(Cs, acc, warp_m, warp_n, lane);
    __syncthreads();
    for (int i = tid; i < 128 * 16; i += 256) {
        int row = i >> 4, col = (i & 15) << 2;
        float4 v = *(float4*)(Cs + row * CPAD + col);
        uint2 h, l; split4(v, h, l);
        size_t o = (size_t)(half * 128 + row) * N_TOK + n0 + col;
        *(uint2*)(g_Fh + o) = h;
        *(uint2*)(g_Fl + o) = l;
    }
}

// ---------------------------------------------------------------------------
// K2: Gpart[z][p][q] ; grid (54, 4): z = 192 tokens, q-tile 64 ; 6 K-chunks
//   buf: A(hi,lo) 128x40 = 10240B each ; B(hi,lo) 64x40 = 5120B each
// ---------------------------------------------------------------------------
#define G_CH 30720
__global__ __launch_bounds__(256, 2)
void k_Gpart()
{
    extern __shared__ __align__(16) char smem[];
    const uint32_t sb = smem_u32(smem);
    float* Cs = (float*)smem;
    const int tid = threadIdx.x, lane = tid & 31, warp = tid >> 5;
    const int warp_m = (warp >> 1) * 32, warp_n = (warp & 1) * 32;
    const int z = blockIdx.x, qt = blockIdx.y;
    const __nv_bfloat16* Ah = g_Fh + (size_t)HDIM * N_TOK + z * 192;
    const __nv_bfloat16* Al = g_Fl + (size_t)HDIM * N_TOK + z * 192;
    const __nv_bfloat16* Bh = g_feat_h + (size_t)(qt * 64) * N_TOK + z * 192;
    const __nv_bfloat16* Bl = g_feat_l + (size_t)(qt * 64) * N_TOK + z * 192;

    float acc[2][4][4] = {};

    auto prefetch = [&](int c, uint32_t buf) {
        stage_cp<128, 32>(buf,         Ah + c * 32, N_TOK, tid);
        stage_cp<128, 32>(buf + 10240, Al + c * 32, N_TOK, tid);
        stage_cp<64, 32>(buf + 20480, Bh + c * 32, N_TOK, tid);
        stage_cp<64, 32>(buf + 25600, Bl + c * 32, N_TOK, tid);
        CP_COMMIT();
    };

    prefetch(0, sb);
    #pragma unroll
    for (int c = 0; c < 6; ++c) {
        uint32_t cur = sb + (c & 1) * G_CH;
        if (c + 1 < 6) { prefetch(c + 1, sb + ((c + 1) & 1) * G_CH); CP_WAIT1(); }
        else           { CP_WAIT0(); }
        __syncthreads();
        mma_chunk<2, 2, false, false, 40, 40>(acc, cur, cur + 10240, cur + 20480, cur + 25600,
                                              warp_m, warp_n, lane);
        __syncthreads();
    }

    acc_to_smem<2, 4>(Cs, acc, warp_m, warp_n, lane);
    __syncthreads();
    float* outp = g_Gpart + (size_t)z * HDIM * CDIM + qt * 64;
    for (int i = tid; i < 128 * 16; i += 256) {
        int row = i >> 4, col = (i & 15) << 2;
        float4 v = *(float4*)(Cs + row * CPAD + col);
        *(float4*)(outp + (size_t)row * CDIM + col) = v;
    }
}

// ---------------------------------------------------------------------------
// K3a: Gpart2[g] = sum of 6 chunks ; grid (32, 9)
// ---------------------------------------------------------------------------
__global__ __launch_bounds__(256)
void k_R1()
{
    const int t = blockIdx.x * 256 + threadIdx.x;
    const int g = blockIdx.y;
    const float4* gp = (const float4*)g_Gpart + (size_t)g * 6 * 8192;
    float4 a0 = {0,0,0,0}, a1 = {0,0,0,0}, a2 = {0,0,0,0};
    #pragma unroll
    for (int z = 0; z < 6; z += 3) {
        float4 v0 = gp[(size_t)z * 8192 + t];
        float4 v1 = gp[(size_t)(z + 1) * 8192 + t];
        float4 v2 = gp[(size_t)(z + 2) * 8192 + t];
        a0.x += v0.x; a0.y += v0.y; a0.z += v0.z; a0.w += v0.w;
        a1.x += v1.x; a1.y += v1.y; a1.z += v1.z; a1.w += v1.w;
        a2.x += v2.x; a2.y += v2.y; a2.z += v2.z; a2.w += v2.w;
    }
    float4 r = make_float4(a0.x + a1.x + a2.x, a0.y + a1.y + a2.y,
                           a0.z + a1.z + a2.z, a0.w + a1.w + a2.w);
    ((float4*)g_Gpart2)[(size_t)g * 8192 + t] = r;
}

// ---------------------------------------------------------------------------
// K3b: G = (1/N) * sum of 9 partials -> bf16 hi/lo planes
// ---------------------------------------------------------------------------
__global__ __launch_bounds__(256)
void k_R2()
{
    const int t = blockIdx.x * 256 + threadIdx.x;
    const float4* gp = (const float4*)g_Gpart2;
    float4 a0 = {0,0,0,0}, a1 = {0,0,0,0}, a2 = {0,0,0,0};
    #pragma unroll
    for (int g = 0; g < 9; g += 3) {
        float4 v0 = gp[(size_t)g * 8192 + t];
        float4 v1 = gp[(size_t)(g + 1) * 8192 + t];
        float4 v2 = gp[(size_t)(g + 2) * 8192 + t];
        a0.x += v0.x; a0.y += v0.y; a0.z += v0.z; a0.w += v0.w;
        a1.x += v1.x; a1.y += v1.y; a1.z += v1.z; a1.w += v1.w;
        a2.x += v2.x; a2.y += v2.y; a2.z += v2.z; a2.w += v2.w;
    }
    const float s = 1.0f / N_TOK;
    float4 r = make_float4((a0.x + a1.x + a2.x) * s, (a0.y + a1.y + a2.y) * s,
                           (a0.z + a1.z + a2.z) * s, (a0.w + a1.w + a2.w) * s);
    uint2 h, l; split4(r, h, l);
    ((uint2*)g_Gh)[t] = h;
    ((uint2*)g_Gl)[t] = l;
}

// ---------------------------------------------------------------------------
// K4: out[q][n] = feat[q][n] + sum_p G[p][q]*Fi[p][n]
//   grid (162, 2): n-tile 64, q-half 128 ; 4 K-chunks of 32 (p)
//   buf: A(hi,lo) 32x136 = 8704B each ; B(hi,lo) 32x72 = 4608B each
// ---------------------------------------------------------------------------
#define O_CH 26624
__global__ __launch_bounds__(256, 2)
void k_out(const float* __restrict__ feat, float* __restrict__ outp)
{
    extern __shared__ __align__(16) char smem[];
    const uint32_t sb = smem_u32(smem);
    float* Cs = (float*)smem;
    const int tid = threadIdx.x, lane = tid & 31, warp = tid >> 5;
    const int warp_m = (warp >> 1) * 32, warp_n = (warp & 1) * 32;
    const int n0 = blockIdx.x * 64, qh = blockIdx.y;

    float acc[2][4][4] = {};

    auto prefetch = [&](int c, uint32_t buf) {
        stage_cp<32, 128>(buf,         g_Gh + (size_t)(c * 32) * CDIM + qh * 128, CDIM, tid);
        stage_cp<32, 128>(buf + 8704,  g_Gl + (size_t)(c * 32) * CDIM + qh * 128, CDIM, tid);
        stage_cp<32, 64>(buf + 17408, g_Fh + (size_t)(c * 32) * N_TOK + n0, N_TOK, tid);
        stage_cp<32, 64>(buf + 22016, g_Fl + (size_t)(c * 32) * N_TOK + n0, N_TOK, tid);
        CP_COMMIT();
    };

    prefetch(0, sb);
    #pragma unroll
    for (int c = 0; c < 4; ++c) {
        uint32_t cur = sb + (c & 1) * O_CH;
        if (c + 1 < 4) { prefetch(c + 1, sb + ((c + 1) & 1) * O_CH); CP_WAIT1(); }
        else           { CP_WAIT0(); }
        __syncthreads();
        mma_chunk<2, 2, true, true, 136, 72>(acc, cur, cur + 8704, cur + 17408, cur + 22016,
                                             warp_m, warp_n, lane);
        __syncthreads();
    }

    acc_to_smem<2, 4>(Cs, acc, warp_m, warp_n, lane);
    __syncthreads();
    for (int i = tid; i < 128 * 16; i += 256) {
        int row = i >> 4, col = (i & 15) << 2;
        size_t off = (size_t)(qh * 128 + row) * N_TOK + n0 + col;
        float4 v = *(float4*)(Cs + row * CPAD + col);
        float4 f = *(const float4*)(feat + off);
        v.x += f.x; v.y += f.y; v.z += f.z; v.w += f.w;
        *(float4*)(outp + off) = v;
    }
}

// ---------------------------------------------------------------------------
extern "C" void kernel_launch(void* const* d_in, const int* in_sizes, int n_in,
                              void* d_out, int out_size)
{
    const float* feat = (const float*)d_in[0];
    const float* Wi   = (const float*)d_in[1];
    const float* bi   = (const float*)d_in[2];
    const float* Wj   = (const float*)d_in[3];
    const float* bj   = (const float*)d_in[4];
    float* outp = (float*)d_out;

    static bool attr_set = false;
    if (!attr_set) {
        cudaFuncSetAttribute(k_F,     cudaFuncAttributeMaxDynamicSharedMemorySize, 2 * F_CH);
        cudaFuncSetAttribute(k_Gpart, cudaFuncAttributeMaxDynamicSharedMemorySize, 2 * G_CH);
        cudaFuncSetAttribute(k_out,   cudaFuncAttributeMaxDynamicSharedMemorySize, 2 * O_CH);
        attr_set = true;
    }

    k_cvt   <<<FEAT_BLK + 64, 256>>>(feat, Wi, Wj);
    k_F     <<<dim3(162, 2), 256, 2 * F_CH>>>(bi, bj);
    k_Gpart <<<dim3(54, 4), 256, 2 * G_CH>>>();
    k_R1    <<<dim3(32, 9), 256>>>();
    k_R2    <<<32, 256>>>();
    k_out   <<<dim3(162, 2), 256, 2 * O_CH>>>(feat, outp);
}